// round 4
// baseline (speedup 1.0000x reference)
#include <cuda_runtime.h>
#include <cuda_bf16.h>
#include <cstdint>
#include <math.h>

// ---------------------------------------------------------------------------
// ClusterLoss fused kernel — legacy tensor core path (mma.sync bf16).
// Base sm_103 target: no tcgen05/TMEM available (ptxas rejects), so we use
// ldmatrix + mma.sync.m16n8k16 (HMMA) with register accumulators.
//
//   loss = mean_i || f_hat_i - C[argmax_k (f_hat_i . c_hat_k)] ||^2
//        = mean_i ( 1 + ||C_a||^2 - 2 * sim_max_i * ||C_a|| )
// ---------------------------------------------------------------------------

#define MAX_K 4096

__device__ __align__(16) __nv_bfloat16 g_cn[MAX_K * 128];  // normalized centers bf16 [K][128]
__device__ float g_norms[MAX_K];                           // ||c_k||
__device__ float g_sum;

// ---------------- helpers ----------------

__device__ __forceinline__ uint32_t smem_u32(const void* p) {
    uint32_t a;
    asm("{ .reg .u64 t; cvta.to.shared.u64 t, %1; cvt.u32.u64 %0, t; }" : "=r"(a) : "l"(p));
    return a;
}

__device__ __forceinline__ void ldmatrix_x4(uint32_t& r0, uint32_t& r1, uint32_t& r2, uint32_t& r3,
                                            uint32_t addr) {
    asm volatile("ldmatrix.sync.aligned.m8n8.x4.shared.b16 {%0,%1,%2,%3}, [%4];"
                 : "=r"(r0), "=r"(r1), "=r"(r2), "=r"(r3) : "r"(addr));
}

__device__ __forceinline__ void mma_bf16(float& c0, float& c1, float& c2, float& c3,
                                         uint32_t a0, uint32_t a1, uint32_t a2, uint32_t a3,
                                         uint32_t b0, uint32_t b1) {
    asm volatile(
        "mma.sync.aligned.m16n8k16.row.col.f32.bf16.bf16.f32 "
        "{%0,%1,%2,%3}, {%4,%5,%6,%7}, {%8,%9}, {%0,%1,%2,%3};"
        : "+f"(c0), "+f"(c1), "+f"(c2), "+f"(c3)
        : "r"(a0), "r"(a1), "r"(a2), "r"(a3), "r"(b0), "r"(b1));
}

// Padded row-major smem tile: 128 rows x 128 bf16, row stride 272 bytes
// (272 mod 128 = 16 -> 8 consecutive rows hit distinct 16B bank groups,
//  conflict-free for ldmatrix; 272 % 16 == 0 keeps rows 16B-aligned).
#define ROW_STRIDE 272

// smem byte offsets
#define SMEM_A    0
#define SMEM_B    34816
#define SMEM_BEST 69632            // float [2][128]
#define SMEM_IDX  70656            // int   [2][128]
#define SMEM_RED  71680            // float [8]
#define SMEM_TOTAL 71744

// ---------------- kernels ----------------

__global__ void zero_kernel() { g_sum = 0.0f; }

// Normalize centers: one warp per row. Writes bf16 normalized row + fp32 norm.
__global__ void __launch_bounds__(256) prep_centers_kernel(const float* __restrict__ centers, int K) {
    int row  = blockIdx.x * 8 + (threadIdx.x >> 5);
    int lane = threadIdx.x & 31;
    if (row >= K) return;
    float4 v = reinterpret_cast<const float4*>(centers)[(size_t)row * 32 + lane];
    float s = v.x * v.x + v.y * v.y + v.z * v.z + v.w * v.w;
    #pragma unroll
    for (int o = 16; o; o >>= 1) s += __shfl_xor_sync(0xffffffffu, s, o);
    float nrm = sqrtf(s);
    float inv = 1.0f / fmaxf(nrm, 1e-12f);
    if (lane == 0) g_norms[row] = nrm;
    __nv_bfloat162 p0 = __floats2bfloat162_rn(v.x * inv, v.y * inv);
    __nv_bfloat162 p1 = __floats2bfloat162_rn(v.z * inv, v.w * inv);
    uint2 w;
    w.x = *reinterpret_cast<uint32_t*>(&p0);
    w.y = *reinterpret_cast<uint32_t*>(&p1);
    reinterpret_cast<uint2*>(g_cn)[(size_t)row * 32 + lane] = w;
}

__global__ void __launch_bounds__(256, 1) main_kernel(const float* __restrict__ features, int K) {
    extern __shared__ char smem[];
    const uint32_t sbase = smem_u32(smem);
    const int tid  = threadIdx.x;
    const int wid  = tid >> 5;
    const int lane = tid & 31;
    const int warpM = wid & 3;      // 4 warps over M (32 rows each)
    const int warpN = wid >> 2;     // 2 warps over N (64 cols each)

    // --- normalize feature tile -> bf16 into A smem ---
    const int rowBase = blockIdx.x * 128;
    for (int r = wid; r < 128; r += 8) {
        float4 v = reinterpret_cast<const float4*>(features)[(size_t)(rowBase + r) * 32 + lane];
        float s = v.x * v.x + v.y * v.y + v.z * v.z + v.w * v.w;
        #pragma unroll
        for (int o = 16; o; o >>= 1) s += __shfl_xor_sync(0xffffffffu, s, o);
        float inv = 1.0f / fmaxf(sqrtf(s), 1e-12f);
        __nv_bfloat162 p0 = __floats2bfloat162_rn(v.x * inv, v.y * inv);
        __nv_bfloat162 p1 = __floats2bfloat162_rn(v.z * inv, v.w * inv);
        uint2 w;
        w.x = *reinterpret_cast<uint32_t*>(&p0);
        w.y = *reinterpret_cast<uint32_t*>(&p1);
        *reinterpret_cast<uint2*>(smem + SMEM_A + r * ROW_STRIDE + lane * 8) = w;
    }
    __syncthreads();

    // --- preload A fragments into registers: 2 m16 tiles x 8 k16 steps x 4 regs ---
    uint32_t afr[2][8][4];
    {
        const int rsel = lane & 15;                 // row within 16-row tile
        const int csel = (lane & 16) ? 16 : 0;      // 16B column half
        #pragma unroll
        for (int m = 0; m < 2; m++) {
            const int rbase = warpM * 32 + m * 16;
            #pragma unroll
            for (int kk = 0; kk < 8; kk++) {
                uint32_t addr = sbase + SMEM_A + (rbase + rsel) * ROW_STRIDE + kk * 32 + csel;
                ldmatrix_x4(afr[m][kk][0], afr[m][kk][1], afr[m][kk][2], afr[m][kk][3], addr);
            }
        }
    }

    float best[4] = {-2.0f, -2.0f, -2.0f, -2.0f};
    int   bidx[4] = {0, 0, 0, 0};
    const int numTiles = K >> 7;
    const uint4* cn4 = reinterpret_cast<const uint4*>(g_cn);

    for (int t = 0; t < numTiles; t++) {
        __syncthreads();   // previous tile's B reads complete
        // --- cooperative load of B tile (128 centers x 128 bf16) ---
        #pragma unroll
        for (int j = 0; j < 8; j++) {
            int ci = tid + 256 * j;         // 0..2047 chunks of 16B
            int r  = ci >> 4;
            int cb = (ci & 15) * 16;
            uint4 d = cn4[((size_t)t * 128 + r) * 16 + (ci & 15)];
            *reinterpret_cast<uint4*>(smem + SMEM_B + r * ROW_STRIDE + cb) = d;
        }
        __syncthreads();

        // --- accumulate sims for this tile ---
        float acc[2][8][4];
        #pragma unroll
        for (int m = 0; m < 2; m++)
            #pragma unroll
            for (int nf = 0; nf < 8; nf++)
                #pragma unroll
                for (int c = 0; c < 4; c++) acc[m][nf][c] = 0.0f;

        const int rsel = lane & 15;
        const int csel = (lane & 16) ? 16 : 0;
        #pragma unroll
        for (int kk = 0; kk < 8; kk++) {
            #pragma unroll
            for (int np = 0; np < 4; np++) {   // each x4 covers n16 x k16
                const int nbase = warpN * 64 + np * 16;
                uint32_t b0, b1, b2, b3;
                uint32_t addr = sbase + SMEM_B + (nbase + rsel) * ROW_STRIDE + kk * 32 + csel;
                ldmatrix_x4(b0, b1, b2, b3, addr);
                #pragma unroll
                for (int m = 0; m < 2; m++) {
                    mma_bf16(acc[m][2*np][0],   acc[m][2*np][1],   acc[m][2*np][2],   acc[m][2*np][3],
                             afr[m][kk][0], afr[m][kk][1], afr[m][kk][2], afr[m][kk][3], b0, b2);
                    mma_bf16(acc[m][2*np+1][0], acc[m][2*np+1][1], acc[m][2*np+1][2], acc[m][2*np+1][3],
                             afr[m][kk][0], afr[m][kk][1], afr[m][kk][2], afr[m][kk][3], b1, b3);
                }
            }
        }

        // --- running argmax update ---
        #pragma unroll
        for (int m = 0; m < 2; m++) {
            #pragma unroll
            for (int nf = 0; nf < 8; nf++) {
                const int colb = t * 128 + warpN * 64 + nf * 8 + (lane & 3) * 2;
                #pragma unroll
                for (int c = 0; c < 4; c++) {
                    const int s   = m * 2 + (c >> 1);
                    const int col = colb + (c & 1);
                    float v = acc[m][nf][c];
                    if (v > best[s] || (v == best[s] && col < bidx[s])) { best[s] = v; bidx[s] = col; }
                }
            }
        }
    }

    // --- quad reduce: row r owned by lanes g*4..g*4+3 ---
    #pragma unroll
    for (int s = 0; s < 4; s++) {
        #pragma unroll
        for (int o = 1; o <= 2; o <<= 1) {
            float ob = __shfl_xor_sync(0xffffffffu, best[s], o);
            int   oi = __shfl_xor_sync(0xffffffffu, bidx[s], o);
            if (ob > best[s] || (ob == best[s] && oi < bidx[s])) { best[s] = ob; bidx[s] = oi; }
        }
    }

    // --- merge across warpN pairs via smem ---
    float* sBest = reinterpret_cast<float*>(smem + SMEM_BEST);
    int*   sIdx  = reinterpret_cast<int*>(smem + SMEM_IDX);
    if ((lane & 3) == 0) {
        #pragma unroll
        for (int s = 0; s < 4; s++) {
            int row = warpM * 32 + (s >> 1) * 16 + (lane >> 2) + (s & 1) * 8;
            sBest[warpN * 128 + row] = best[s];
            sIdx [warpN * 128 + row] = bidx[s];
        }
    }
    __syncthreads();

    float loss = 0.0f;
    if (tid < 128) {
        float b0 = sBest[tid],        b1 = sBest[128 + tid];
        int   i0 = sIdx[tid],         i1 = sIdx[128 + tid];
        float bb = b0; int ii = i0;
        if (b1 > bb || (b1 == bb && i1 < ii)) { bb = b1; ii = i1; }
        float nrm = g_norms[ii];
        loss = 1.0f + nrm * nrm - 2.0f * bb * nrm;
    }
    #pragma unroll
    for (int o = 16; o; o >>= 1) loss += __shfl_xor_sync(0xffffffffu, loss, o);
    float* sRed = reinterpret_cast<float*>(smem + SMEM_RED);
    if (lane == 0) sRed[wid] = loss;
    __syncthreads();
    if (tid == 0) {
        float tot = sRed[0] + sRed[1] + sRed[2] + sRed[3];
        atomicAdd(&g_sum, tot);   // warps 4-7 contributed zero (tid>=128)
    }
}

__global__ void finalize_kernel(float* out, float invN) { out[0] = g_sum * invN; }

// ---------------- launch ----------------

extern "C" void kernel_launch(void* const* d_in, const int* in_sizes, int n_in,
                              void* d_out, int out_size) {
    const float* features = (const float*)d_in[0];
    const float* centers  = (const float*)d_in[1];
    const int N = in_sizes[0] / 128;
    const int K = in_sizes[1] / 128;

    cudaFuncSetAttribute(main_kernel, cudaFuncAttributeMaxDynamicSharedMemorySize, SMEM_TOTAL);

    zero_kernel<<<1, 1>>>();
    prep_centers_kernel<<<(K + 7) / 8, 256>>>(centers, K);
    main_kernel<<<N / 128, 256, SMEM_TOTAL>>>(features, K);
    finalize_kernel<<<1, 1>>>((float*)d_out, 1.0f / (float)N);
}

// round 5
// speedup vs baseline: 1.3357x; 1.3357x over previous
#include <cuda_runtime.h>
#include <cuda_bf16.h>
#include <cstdint>
#include <math.h>

// ---------------------------------------------------------------------------
// ClusterLoss fused kernel — legacy tensor core path (mma.sync bf16),
// cp.async double-buffered B tiles, occupancy 2.
//
//   loss = mean_i || f_hat_i - C[argmax_k (f_hat_i . c_hat_k)] ||^2
//        = mean_i ( 1 + ||C_a||^2 - 2 * sim_max_i * ||C_a|| )
// ---------------------------------------------------------------------------

#define MAX_K 4096

__device__ __align__(16) __nv_bfloat16 g_cn[MAX_K * 128];  // normalized centers bf16 [K][128]
__device__ float g_norms[MAX_K];                           // ||c_k||
__device__ float g_sum;

// ---------------- helpers ----------------

__device__ __forceinline__ uint32_t smem_u32(const void* p) {
    uint32_t a;
    asm("{ .reg .u64 t; cvta.to.shared.u64 t, %1; cvt.u32.u64 %0, t; }" : "=r"(a) : "l"(p));
    return a;
}

__device__ __forceinline__ void ldmatrix_x4(uint32_t& r0, uint32_t& r1, uint32_t& r2, uint32_t& r3,
                                            uint32_t addr) {
    asm volatile("ldmatrix.sync.aligned.m8n8.x4.shared.b16 {%0,%1,%2,%3}, [%4];"
                 : "=r"(r0), "=r"(r1), "=r"(r2), "=r"(r3) : "r"(addr));
}

__device__ __forceinline__ void mma_bf16(float& c0, float& c1, float& c2, float& c3,
                                         uint32_t a0, uint32_t a1, uint32_t a2, uint32_t a3,
                                         uint32_t b0, uint32_t b1) {
    asm volatile(
        "mma.sync.aligned.m16n8k16.row.col.f32.bf16.bf16.f32 "
        "{%0,%1,%2,%3}, {%4,%5,%6,%7}, {%8,%9}, {%0,%1,%2,%3};"
        : "+f"(c0), "+f"(c1), "+f"(c2), "+f"(c3)
        : "r"(a0), "r"(a1), "r"(a2), "r"(a3), "r"(b0), "r"(b1));
}

__device__ __forceinline__ void cp_async16(uint32_t dst, const void* src) {
    asm volatile("cp.async.cg.shared.global [%0], [%1], 16;" :: "r"(dst), "l"(src));
}
#define CP_COMMIT() asm volatile("cp.async.commit_group;" ::: "memory")
#define CP_WAIT0()  asm volatile("cp.async.wait_group 0;" ::: "memory")

// Padded row-major smem tile: 128 rows x 128 bf16, row stride 272 bytes
// (272 mod 128 = 16 -> consecutive rows land on distinct 16B bank groups,
//  conflict-free ldmatrix; 272 % 16 == 0 keeps 16B alignment for cp.async).
#define ROW_STRIDE 272

// smem byte offsets
#define SMEM_A     0
#define SMEM_B0    34816
#define SMEM_B1    69632
#define SMEM_BEST  104448          // float [2][128]
#define SMEM_IDX   105472          // int   [2][128]
#define SMEM_RED   106496          // float [8]
#define SMEM_TOTAL 106560

// ---------------- kernels ----------------

__global__ void zero_kernel() { g_sum = 0.0f; }

// Normalize centers: one warp per row. Writes bf16 normalized row + fp32 norm.
__global__ void __launch_bounds__(256) prep_centers_kernel(const float* __restrict__ centers, int K) {
    int row  = blockIdx.x * 8 + (threadIdx.x >> 5);
    int lane = threadIdx.x & 31;
    if (row >= K) return;
    float4 v = reinterpret_cast<const float4*>(centers)[(size_t)row * 32 + lane];
    float s = v.x * v.x + v.y * v.y + v.z * v.z + v.w * v.w;
    #pragma unroll
    for (int o = 16; o; o >>= 1) s += __shfl_xor_sync(0xffffffffu, s, o);
    float nrm = sqrtf(s);
    float inv = 1.0f / fmaxf(nrm, 1e-12f);
    if (lane == 0) g_norms[row] = nrm;
    __nv_bfloat162 p0 = __floats2bfloat162_rn(v.x * inv, v.y * inv);
    __nv_bfloat162 p1 = __floats2bfloat162_rn(v.z * inv, v.w * inv);
    uint2 w;
    w.x = *reinterpret_cast<uint32_t*>(&p0);
    w.y = *reinterpret_cast<uint32_t*>(&p1);
    reinterpret_cast<uint2*>(g_cn)[(size_t)row * 32 + lane] = w;
}

__global__ void __launch_bounds__(256, 2) main_kernel(const float* __restrict__ features, int K) {
    extern __shared__ char smem[];
    const uint32_t sbase = smem_u32(smem);
    const int tid  = threadIdx.x;
    const int wid  = tid >> 5;
    const int lane = tid & 31;
    const int warpM = wid & 3;      // 4 warps over M (32 rows each)
    const int warpN = wid >> 2;     // 2 warps over N (64 cols each)

    const int numTiles = K >> 7;
    const char* cn = reinterpret_cast<const char*>(g_cn);

    // --- issue cp.async for B tile 0 immediately (overlaps normalize) ---
    {
        const uint32_t bbuf = sbase + SMEM_B0;
        #pragma unroll
        for (int j = 0; j < 8; j++) {
            int ci = tid + 256 * j;           // 0..2047 x 16B chunks
            int r  = ci >> 4;
            int cb = (ci & 15) * 16;
            cp_async16(bbuf + r * ROW_STRIDE + cb, cn + (size_t)r * 256 + cb);
        }
        CP_COMMIT();
    }

    // --- normalize feature tile -> bf16 into A smem ---
    const int rowBase = blockIdx.x * 128;
    for (int r = wid; r < 128; r += 8) {
        float4 v = reinterpret_cast<const float4*>(features)[(size_t)(rowBase + r) * 32 + lane];
        float s = v.x * v.x + v.y * v.y + v.z * v.z + v.w * v.w;
        #pragma unroll
        for (int o = 16; o; o >>= 1) s += __shfl_xor_sync(0xffffffffu, s, o);
        float inv = 1.0f / fmaxf(sqrtf(s), 1e-12f);
        __nv_bfloat162 p0 = __floats2bfloat162_rn(v.x * inv, v.y * inv);
        __nv_bfloat162 p1 = __floats2bfloat162_rn(v.z * inv, v.w * inv);
        uint2 w;
        w.x = *reinterpret_cast<uint32_t*>(&p0);
        w.y = *reinterpret_cast<uint32_t*>(&p1);
        *reinterpret_cast<uint2*>(smem + SMEM_A + r * ROW_STRIDE + lane * 8) = w;
    }

    float best[4] = {-2.0f, -2.0f, -2.0f, -2.0f};
    int   bidx[4] = {0, 0, 0, 0};

    const int rsel = lane & 15;
    const int csel = (lane & 16) ? 16 : 0;
    const uint32_t aAddr = sbase + SMEM_A + (warpM * 32 + rsel) * ROW_STRIDE + csel;
    const uint32_t bAddr0 = sbase + (warpN * 64 + rsel) * ROW_STRIDE + csel;

    for (int t = 0; t < numTiles; t++) {
        CP_WAIT0();          // B tile t resident
        __syncthreads();     // all warps' prev-tile reads done + tile t visible

        // --- prefetch B tile t+1 into the other buffer ---
        if (t + 1 < numTiles) {
            const uint32_t bbuf = sbase + (((t + 1) & 1) ? SMEM_B1 : SMEM_B0);
            const char* src = cn + (size_t)(t + 1) * 128 * 256;
            #pragma unroll
            for (int j = 0; j < 8; j++) {
                int ci = tid + 256 * j;
                int r  = ci >> 4;
                int cb = (ci & 15) * 16;
                cp_async16(bbuf + r * ROW_STRIDE + cb, src + (size_t)r * 256 + cb);
            }
        }
        CP_COMMIT();         // commit (possibly empty) group so wait_group 0 pairs up

        // --- MMA on tile t ---
        const uint32_t bb = bAddr0 + ((t & 1) ? SMEM_B1 : SMEM_B0);

        float acc[2][8][4];
        #pragma unroll
        for (int m = 0; m < 2; m++)
            #pragma unroll
            for (int nf = 0; nf < 8; nf++)
                #pragma unroll
                for (int c = 0; c < 4; c++) acc[m][nf][c] = 0.0f;

        #pragma unroll
        for (int kk = 0; kk < 8; kk++) {
            uint32_t af[2][4];
            #pragma unroll
            for (int m = 0; m < 2; m++)
                ldmatrix_x4(af[m][0], af[m][1], af[m][2], af[m][3],
                            aAddr + m * 16 * ROW_STRIDE + kk * 32);
            #pragma unroll
            for (int np = 0; np < 4; np++) {
                uint32_t b0, b1, b2, b3;
                ldmatrix_x4(b0, b1, b2, b3, bb + np * 16 * ROW_STRIDE + kk * 32);
                #pragma unroll
                for (int m = 0; m < 2; m++) {
                    mma_bf16(acc[m][2*np][0],   acc[m][2*np][1],   acc[m][2*np][2],   acc[m][2*np][3],
                             af[m][0], af[m][1], af[m][2], af[m][3], b0, b2);
                    mma_bf16(acc[m][2*np+1][0], acc[m][2*np+1][1], acc[m][2*np+1][2], acc[m][2*np+1][3],
                             af[m][0], af[m][1], af[m][2], af[m][3], b1, b3);
                }
            }
        }

        // --- running argmax update ---
        #pragma unroll
        for (int m = 0; m < 2; m++) {
            #pragma unroll
            for (int nf = 0; nf < 8; nf++) {
                const int colb = t * 128 + warpN * 64 + nf * 8 + (lane & 3) * 2;
                #pragma unroll
                for (int c = 0; c < 4; c++) {
                    const int s   = m * 2 + (c >> 1);
                    const int col = colb + (c & 1);
                    float v = acc[m][nf][c];
                    if (v > best[s] || (v == best[s] && col < bidx[s])) { best[s] = v; bidx[s] = col; }
                }
            }
        }
    }

    // --- quad reduce: row r owned by lanes g*4..g*4+3 ---
    #pragma unroll
    for (int s = 0; s < 4; s++) {
        #pragma unroll
        for (int o = 1; o <= 2; o <<= 1) {
            float ob = __shfl_xor_sync(0xffffffffu, best[s], o);
            int   oi = __shfl_xor_sync(0xffffffffu, bidx[s], o);
            if (ob > best[s] || (ob == best[s] && oi < bidx[s])) { best[s] = ob; bidx[s] = oi; }
        }
    }

    // --- merge across warpN pairs via smem ---
    float* sBest = reinterpret_cast<float*>(smem + SMEM_BEST);
    int*   sIdx  = reinterpret_cast<int*>(smem + SMEM_IDX);
    __syncthreads();
    if ((lane & 3) == 0) {
        #pragma unroll
        for (int s = 0; s < 4; s++) {
            int row = warpM * 32 + (s >> 1) * 16 + (lane >> 2) + (s & 1) * 8;
            sBest[warpN * 128 + row] = best[s];
            sIdx [warpN * 128 + row] = bidx[s];
        }
    }
    __syncthreads();

    float loss = 0.0f;
    if (tid < 128) {
        float b0 = sBest[tid],        b1 = sBest[128 + tid];
        int   i0 = sIdx[tid],         i1 = sIdx[128 + tid];
        float bb = b0; int ii = i0;
        if (b1 > bb || (b1 == bb && i1 < ii)) { bb = b1; ii = i1; }
        float nrm = g_norms[ii];
        loss = 1.0f + nrm * nrm - 2.0f * bb * nrm;
    }
    #pragma unroll
    for (int o = 16; o; o >>= 1) loss += __shfl_xor_sync(0xffffffffu, loss, o);
    float* sRed = reinterpret_cast<float*>(smem + SMEM_RED);
    if (lane == 0) sRed[wid] = loss;
    __syncthreads();
    if (tid == 0) {
        float tot = sRed[0] + sRed[1] + sRed[2] + sRed[3];
        atomicAdd(&g_sum, tot);   // warps 4-7 contributed zero (tid>=128)
    }
}

__global__ void finalize_kernel(float* out, float invN) { out[0] = g_sum * invN; }

// ---------------- launch ----------------

extern "C" void kernel_launch(void* const* d_in, const int* in_sizes, int n_in,
                              void* d_out, int out_size) {
    const float* features = (const float*)d_in[0];
    const float* centers  = (const float*)d_in[1];
    const int N = in_sizes[0] / 128;
    const int K = in_sizes[1] / 128;

    cudaFuncSetAttribute(main_kernel, cudaFuncAttributeMaxDynamicSharedMemorySize, SMEM_TOTAL);

    zero_kernel<<<1, 1>>>();
    prep_centers_kernel<<<(K + 7) / 8, 256>>>(centers, K);
    main_kernel<<<N / 128, 256, SMEM_TOTAL>>>(features, K);
    finalize_kernel<<<1, 1>>>((float*)d_out, 1.0f / (float)N);
}